// round 3
// baseline (speedup 1.0000x reference)
#include <cuda_runtime.h>
#include <math.h>

#define NATOM 32768
#define KNBR 16
#define NEDGE (NATOM*KNBR)

__device__ __align__(16) float g_basis[(size_t)NEDGE*10];
__device__ __align__(16) float g_Y[(size_t)NEDGE*16];
__device__ __align__(16) float g_w[(size_t)NEDGE*256];
__device__ __align__(16) float g_featA[(size_t)NATOM*64];
__device__ __align__(16) float g_featB[(size_t)NATOM*64];
__device__ float g_part[64*64];

__global__ void geom_kernel(const float* __restrict__ coords,
                            const float* __restrict__ shift,
                            const int*   __restrict__ nbr)
{
    int e = blockIdx.x*blockDim.x + threadIdx.x;
    if (e >= NEDGE) return;
    int n  = e >> 4;
    int nb = nbr[e];
    float x = coords[3*nb+0] + shift[3*(size_t)e+0] - coords[3*n+0];
    float y = coords[3*nb+1] + shift[3*(size_t)e+1] - coords[3*n+1];
    float z = coords[3*nb+2] + shift[3*(size_t)e+2] - coords[3*n+2];
    float r  = sqrtf(x*x + y*y + z*z);
    float inv = 1.0f/fmaxf(r, 1e-6f);
    float dx = x*inv, dy = y*inv, dz = z*inv;
    float x2 = dx*dx, y2 = dy*dy, z2 = dz*dz;
    float Y[16];
    Y[0]=0.4886025f*dy; Y[1]=0.4886025f*dz; Y[2]=0.4886025f*dx;
    Y[3]=1.0925484f*dx*dy; Y[4]=1.0925484f*dy*dz; Y[5]=0.3153916f*(3.f*z2-1.f);
    Y[6]=1.0925484f*dx*dz; Y[7]=0.5462742f*(x2-y2);
    Y[8]=0.5900436f*dy*(3.f*x2-y2); Y[9]=2.8906114f*dx*dy*dz;
    Y[10]=0.4570458f*dy*(5.f*z2-1.f); Y[11]=0.3731763f*dz*(5.f*z2-3.f);
    Y[12]=0.4570458f*dx*(5.f*z2-1.f); Y[13]=1.4453057f*(x2-y2)*dz;
    Y[14]=0.5900436f*dx*(x2-3.f*y2); Y[15]=0.f;
    float* Yp = g_Y + (size_t)e*16;
#pragma unroll
    for (int q=0;q<4;q++)
        *(float4*)(Yp+4*q) = make_float4(Y[4*q],Y[4*q+1],Y[4*q+2],Y[4*q+3]);
    float mask = (r < 2.0f && r > 1e-6f) ? 1.f : 0.f;
    const float step = 2.0f/9.0f, invstep = 4.5f;
    float* bp = g_basis + (size_t)e*10;
#pragma unroll
    for (int b=0;b<10;b++) {
        float xr = (r - (float)b*step)*invstep;
        float v = 0.f;
        if (fabsf(xr) < 1.0f) { float c = cospif(0.5f*xr); v = c*c; }
        bp[b] = v*mask;
    }
}

#define SMEM_FLOATS (1000+12800+12800+16384)
#define SMEM_BYTES  (SMEM_FLOATS*4)

template<int NW>
__global__ void __launch_bounds__(512) radial_kernel(
    const float* __restrict__ W1, const float* __restrict__ W2,
    const float* __restrict__ W3)
{
    extern __shared__ float sm[];
    float* s_w1 = sm;          // [10][100]
    float* s_wB = sm + 1000;   // [100][128]
    float* s_h1 = sm + 13800;  // [k][e] 100x128
    float* s_h2 = sm + 26600;  // [e][j] 128x128 (head reused for basis)
    const int tid = threadIdx.x;
    const int tx = tid & 31, ty = tid >> 5;
    const int j0 = tx*4, e0 = ty*8;
    const size_t ebase = (size_t)blockIdx.x*128;

    for (int i = tid; i < 1000; i += 512) s_w1[i] = W1[i];
    __syncthreads();
    for (int i = tid; i < 1280; i += 512) s_h2[i] = g_basis[ebase*10 + i];
    __syncthreads();
    for (int i = tid; i < 12800; i += 512) {
        int k = i >> 7, c = i & 127;
        float a = 0.f;
#pragma unroll
        for (int b = 0; b < 10; b++) a += s_h2[c*10+b]*s_w1[b*100+k];
        s_h1[i] = fmaxf(a, 0.f);
        s_wB[i] = (c < 100) ? W2[k*100+c] : 0.f;
    }
    __syncthreads();
    {
        float acc[8][4];
#pragma unroll
        for (int a=0;a<8;a++)
#pragma unroll
            for (int b=0;b<4;b++) acc[a][b]=0.f;
        for (int k = 0; k < 100; k++) {
            float4 w = *(const float4*)&s_wB[k*128 + j0];
#pragma unroll
            for (int ee=0;ee<8;ee++) {
                float h = s_h1[k*128 + e0 + ee];
                acc[ee][0] += h*w.x; acc[ee][1] += h*w.y;
                acc[ee][2] += h*w.z; acc[ee][3] += h*w.w;
            }
        }
#pragma unroll
        for (int ee=0;ee<8;ee++)
            *(float4*)&s_h2[(e0+ee)*128 + j0] =
                make_float4(fmaxf(acc[ee][0],0.f), fmaxf(acc[ee][1],0.f),
                            fmaxf(acc[ee][2],0.f), fmaxf(acc[ee][3],0.f));
    }
    __syncthreads();
    for (int cb = 0; cb < NW; cb += 128) {
        const int cw = (NW - cb) < 128 ? (NW - cb) : 128;
        for (int i = tid; i < 12800; i += 512) {
            int k = i >> 7, j = i & 127;
            s_wB[i] = (j < cw) ? W3[k*NW + cb + j] : 0.f;
        }
        __syncthreads();
        float acc[8][4];
#pragma unroll
        for (int a=0;a<8;a++)
#pragma unroll
            for (int b=0;b<4;b++) acc[a][b]=0.f;
        for (int k = 0; k < 100; k++) {
            float4 w = *(const float4*)&s_wB[k*128 + j0];
#pragma unroll
            for (int ee=0;ee<8;ee++) {
                float h = s_h2[(e0+ee)*128 + k];
                acc[ee][0] += h*w.x; acc[ee][1] += h*w.y;
                acc[ee][2] += h*w.z; acc[ee][3] += h*w.w;
            }
        }
        if (j0 < cw) {
#pragma unroll
            for (int ee=0;ee<8;ee++)
                *(float4*)&g_w[(ebase+e0+ee)*NW + cb + j0] =
                    make_float4(acc[ee][0],acc[ee][1],acc[ee][2],acc[ee][3]);
        }
        __syncthreads();
    }
}

__device__ __forceinline__ float red16(float v) {
    v += __shfl_xor_sync(0xffffffffu, v, 8);
    v += __shfl_xor_sync(0xffffffffu, v, 4);
    v += __shfl_xor_sync(0xffffffffu, v, 2);
    v += __shfl_xor_sync(0xffffffffu, v, 1);
    return v;
}
__constant__ int c_ML[3] = {3,5,7};
__constant__ int c_AO[3] = {0,12,32};
__constant__ int c_YO[3] = {0,3,8};
__constant__ int c_FO[3] = {4,16,36};

__device__ __forceinline__ void gate_write(float* fo, const float* out0,
                                           const float* acc)
{
#pragma unroll
    for (int o=0;o<4;o++) fo[o] = fmaxf(out0[o], 0.f);
    float g[12];
#pragma unroll
    for (int j=0;j<12;j++) g[j] = 1.f/(1.f + expf(-out0[4+j]));
#pragma unroll
    for (int l=0;l<3;l++)
#pragma unroll
        for (int o=0;o<4;o++)
#pragma unroll
            for (int m=0;m<7;m++)
                if (m < c_ML[l])
                    fo[c_FO[l] + o*c_ML[l] + m] =
                        acc[c_AO[l] + o*c_ML[l] + m] * g[l*4+o];
}

__global__ void __launch_bounds__(256) conv0_kernel()
{
    int gt = blockIdx.x*blockDim.x + threadIdx.x;
    int atom = gt >> 4, sub = gt & 15;
    size_t e = (size_t)atom*KNBR + sub;
    const float* wp = g_w + e*28;
    const float* Yp = g_Y + e*16;
    float Y[15];
#pragma unroll
    for (int m=0;m<15;m++) Y[m] = Yp[m];
    float out0[16];
#pragma unroll
    for (int o=0;o<16;o++) out0[o] = red16(wp[o]*0.5f);
    float acc[60];
#pragma unroll
    for (int l=0;l<3;l++)
#pragma unroll
        for (int o=0;o<4;o++) {
            float s = wp[16 + l*4 + o]*0.5f;
#pragma unroll
            for (int m=0;m<7;m++)
                if (m < c_ML[l])
                    acc[c_AO[l]+o*c_ML[l]+m] = red16(s*Y[c_YO[l]+m]);
        }
    if (sub == 0) gate_write(g_featA + (size_t)atom*64, out0, acc);
}

__global__ void __launch_bounds__(256) conv12_kernel(const int* __restrict__ nbr, int dir)
{
    const float* fin = dir ? g_featB : g_featA;
    float* fout      = dir ? g_featA : g_featB;
    int gt = blockIdx.x*blockDim.x + threadIdx.x;
    int atom = gt >> 4, sub = gt & 15;
    size_t e = (size_t)atom*KNBR + sub;
    int nb = nbr[e];
    const float* wp = g_w + e*160;
    const float* Yp = g_Y + e*16;
    const float* fj = fin + (size_t)nb*64;
    float Y[15];
#pragma unroll
    for (int m=0;m<15;m++) Y[m] = Yp[m];
    float f0[4];
#pragma unroll
    for (int i=0;i<4;i++) f0[i] = 0.5f*fj[i];
    float out0[16];
#pragma unroll
    for (int o=0;o<16;o++)
        out0[o] = red16(wp[o*4]*f0[0] + wp[o*4+1]*f0[1] +
                        wp[o*4+2]*f0[2] + wp[o*4+3]*f0[3]);
    float acc[60];
#pragma unroll
    for (int l=0;l<3;l++) {
        float fl[28];
#pragma unroll
        for (int q=0;q<28;q++)
            if (q < 4*c_ML[l]) fl[q] = 0.5f*fj[c_FO[l]+q];
#pragma unroll
        for (int o=0;o<4;o++) {
            const float* wB = wp + 64 + l*32 + o*4;
            float s = wB[0]*f0[0]+wB[1]*f0[1]+wB[2]*f0[2]+wB[3]*f0[3];
            const float* wA = wp + 64 + l*32 + 16 + o*4;
#pragma unroll
            for (int m=0;m<7;m++)
                if (m < c_ML[l]) {
                    float v = s*Y[c_YO[l]+m];
#pragma unroll
                    for (int i=0;i<4;i++) v += wA[i]*fl[i*c_ML[l]+m];
                    acc[c_AO[l]+o*c_ML[l]+m] = red16(v);
                }
        }
    }
    if (sub == 0) gate_write(fout + (size_t)atom*64, out0, acc);
}

__global__ void __launch_bounds__(256) conv3_kernel(const int* __restrict__ nbr)
{
    int gt = blockIdx.x*blockDim.x + threadIdx.x;
    int atom = gt >> 4, sub = gt & 15;
    size_t e = (size_t)atom*KNBR + sub;
    int nb = nbr[e];
    const float* wp = g_w + e*256;
    const float* fj = g_featA + (size_t)nb*64;
    float f0[4];
#pragma unroll
    for (int i=0;i<4;i++) f0[i] = 0.5f*fj[i];
#pragma unroll
    for (int o=0;o<64;o++) {
        float v = wp[o*4]*f0[0] + wp[o*4+1]*f0[1] +
                  wp[o*4+2]*f0[2] + wp[o*4+3]*f0[3];
        v = red16(v);
        if (sub == 0) g_featB[(size_t)atom*64 + o] = fmaxf(v, 0.f);
    }
}

__global__ void pool1_kernel()
{
    __shared__ float sm[256];
    int b = blockIdx.x, tid = threadIdx.x, t = tid >> 6, f = tid & 63;
    float s = 0.f;
    for (int a = b*512 + t; a < (b+1)*512; a += 4)
        s += g_featB[(size_t)a*64 + f];
    sm[tid] = s;
    __syncthreads();
    if (t == 0) g_part[b*64+f] = sm[f] + sm[64+f] + sm[128+f] + sm[192+f];
}
__global__ void pool2_kernel(const float* __restrict__ lw,
                             const float* __restrict__ lb, float* out)
{
    __shared__ float pooled[64];
    int tid = threadIdx.x;
    if (tid < 64) {
        float s = 0.f;
        for (int b=0;b<64;b++) s += g_part[b*64+tid];
        pooled[tid] = s*(1.f/32768.f);
    }
    __syncthreads();
    if (tid < 10) {
        float s = lb[tid];
        for (int f=0;f<64;f++) s += pooled[f]*lw[f*10+tid];
        out[tid] = s;
    }
}

extern "C" void kernel_launch(void* const* d_in, const int* in_sizes, int n_in,
                              void* d_out, int out_size)
{
    const float *coords=0,*shift=0,*lw=0,*lb=0;
    const float *w1[4]={0,0,0,0}, *w2[4]={0,0,0,0}, *w3[4]={0,0,0,0};
    const int* nbr=0;
    int n1=0, n2=0, n3m=0;
    for (int i=0;i<n_in;i++) {
        switch (in_sizes[i]) {
            case 98304:   coords = (const float*)d_in[i]; break;
            case 1572864: shift  = (const float*)d_in[i]; break;
            case 524288:  nbr    = (const int*)d_in[i];   break;
            case 1000:    if (n1<4) w1[n1++] = (const float*)d_in[i]; break;
            case 10000:   if (n2<4) w2[n2++] = (const float*)d_in[i]; break;
            case 2800:    w3[0] = (const float*)d_in[i];  break;   // (100,28)
            case 16000:   if (n3m<2) w3[1+n3m++] = (const float*)d_in[i]; break; // (100,160)
            case 25600:   w3[3] = (const float*)d_in[i];  break;   // (100,256)
            case 640:     lw = (const float*)d_in[i];     break;
            case 10:      lb = (const float*)d_in[i];     break;
            default: break;
        }
    }
    // fail safe: if any required pointer is missing, do nothing rather than crash
    if (!coords || !shift || !nbr || !lw || !lb ||
        !w1[0]||!w1[1]||!w1[2]||!w1[3] || !w2[0]||!w2[1]||!w2[2]||!w2[3] ||
        !w3[0]||!w3[1]||!w3[2]||!w3[3]) {
        // still launch a trivial kernel so graph capture records work
        pool2_kernel<<<1, 128>>>(lw ? lw : (const float*)d_in[0],
                                 lb ? lb : (const float*)d_in[0], (float*)d_out);
        return;
    }
    float* out = (float*)d_out;

    cudaFuncSetAttribute(radial_kernel<28>,  cudaFuncAttributeMaxDynamicSharedMemorySize, SMEM_BYTES);
    cudaFuncSetAttribute(radial_kernel<160>, cudaFuncAttributeMaxDynamicSharedMemorySize, SMEM_BYTES);
    cudaFuncSetAttribute(radial_kernel<256>, cudaFuncAttributeMaxDynamicSharedMemorySize, SMEM_BYTES);

    geom_kernel<<<NEDGE/256, 256>>>(coords, shift, nbr);
    radial_kernel<28><<<NEDGE/128, 512, SMEM_BYTES>>>(w1[0], w2[0], w3[0]);
    conv0_kernel<<<NATOM*16/256, 256>>>();
    radial_kernel<160><<<NEDGE/128, 512, SMEM_BYTES>>>(w1[1], w2[1], w3[1]);
    conv12_kernel<<<NATOM*16/256, 256>>>(nbr, 0);
    radial_kernel<160><<<NEDGE/128, 512, SMEM_BYTES>>>(w1[2], w2[2], w3[2]);
    conv12_kernel<<<NATOM*16/256, 256>>>(nbr, 1);
    radial_kernel<256><<<NEDGE/128, 512, SMEM_BYTES>>>(w1[3], w2[3], w3[3]);
    conv3_kernel<<<NATOM*16/256, 256>>>(nbr);
    pool1_kernel<<<64, 256>>>();
    pool2_kernel<<<1, 128>>>(lw, lb, out);
}

// round 5
// speedup vs baseline: 1.3811x; 1.3811x over previous
#include <cuda_runtime.h>
#include <math.h>

#define NATOM 32768
#define KNBR 16
#define NEDGE (NATOM*KNBR)

__device__ __align__(16) float g_basisT[(size_t)10*NEDGE];   // [b][e]
__device__ __align__(16) float g_Y[(size_t)NEDGE*16];
__device__ __align__(16) float g_wT[(size_t)256*NEDGE];      // [j][e] per layer
__device__ __align__(16) float g_featA[(size_t)NATOM*64];
__device__ __align__(16) float g_featB[(size_t)NATOM*64];
__device__ float g_part[64*64];

__global__ void geom_kernel(const float* __restrict__ coords,
                            const float* __restrict__ shift,
                            const int*   __restrict__ nbr)
{
    int e = blockIdx.x*blockDim.x + threadIdx.x;
    if (e >= NEDGE) return;
    int n  = e >> 4;
    int nb = nbr[e];
    float x = coords[3*nb+0] + shift[3*(size_t)e+0] - coords[3*n+0];
    float y = coords[3*nb+1] + shift[3*(size_t)e+1] - coords[3*n+1];
    float z = coords[3*nb+2] + shift[3*(size_t)e+2] - coords[3*n+2];
    float r  = sqrtf(x*x + y*y + z*z);
    float inv = 1.0f/fmaxf(r, 1e-6f);
    float dx = x*inv, dy = y*inv, dz = z*inv;
    float x2 = dx*dx, y2 = dy*dy, z2 = dz*dz;
    float Y[16];
    Y[0]=0.4886025f*dy; Y[1]=0.4886025f*dz; Y[2]=0.4886025f*dx;
    Y[3]=1.0925484f*dx*dy; Y[4]=1.0925484f*dy*dz; Y[5]=0.3153916f*(3.f*z2-1.f);
    Y[6]=1.0925484f*dx*dz; Y[7]=0.5462742f*(x2-y2);
    Y[8]=0.5900436f*dy*(3.f*x2-y2); Y[9]=2.8906114f*dx*dy*dz;
    Y[10]=0.4570458f*dy*(5.f*z2-1.f); Y[11]=0.3731763f*dz*(5.f*z2-3.f);
    Y[12]=0.4570458f*dx*(5.f*z2-1.f); Y[13]=1.4453057f*(x2-y2)*dz;
    Y[14]=0.5900436f*dx*(x2-3.f*y2); Y[15]=0.f;
    float* Yp = g_Y + (size_t)e*16;
#pragma unroll
    for (int q=0;q<4;q++)
        *(float4*)(Yp+4*q) = make_float4(Y[4*q],Y[4*q+1],Y[4*q+2],Y[4*q+3]);
    float mask = (r < 2.0f && r > 1e-6f) ? 1.f : 0.f;
    const float step = 2.0f/9.0f, invstep = 4.5f;
#pragma unroll
    for (int b=0;b<10;b++) {
        float xr = (r - (float)b*step)*invstep;
        float v = 0.f;
        if (fabsf(xr) < 1.0f) { float c = cospif(0.5f*xr); v = c*c; }
        g_basisT[(size_t)b*NEDGE + e] = v*mask;
    }
}

// smem: s_w1[1000] | s_wB[100][128] | s_h1[100][128] ([k][e]) | s_h2[100][128] ([j][e])
#define SMEM_FLOATS (1000+12800+12800+12800)
#define SMEM_BYTES  (SMEM_FLOATS*4)

template<int NW>
__global__ void __launch_bounds__(512) radial_kernel(
    const float* __restrict__ W1, const float* __restrict__ W2,
    const float* __restrict__ W3)
{
    extern __shared__ float sm[];
    float* s_w1 = sm;           // [10][100]
    float* s_wB = sm + 1000;    // [k][j] 100x128
    float* s_h1 = sm + 13800;   // [k][e] 100x128
    float* s_h2 = sm + 26600;   // [j][e] 100x128 (head reused for basisT)
    float* s_bT = s_h2;         // [b][e] 10x128
    const int tid = threadIdx.x;
    const int e0 = (tid & 31) * 4;   // lanes span edges  -> conflict-free LDS.128
    const int j0 = (tid >> 5) * 8;   // warp owns 8 outputs -> broadcast weight loads
    const size_t ebase = (size_t)blockIdx.x*128;

    for (int i = tid; i < 1000; i += 512) s_w1[i] = W1[i];
    for (int i = tid; i < 1280; i += 512) {
        int b = i >> 7, e = i & 127;
        s_bT[b*128 + e] = g_basisT[(size_t)b*NEDGE + ebase + e];
    }
    __syncthreads();

    // phase A: h1[k][e] = relu(basis @ W1); also stage W2
    for (int i = tid; i < 12800; i += 512) {
        int k = i >> 7, j = i & 127;
        s_wB[i] = (j < 100) ? W2[k*100 + j] : 0.f;
    }
    for (int iq = tid; iq < 3200; iq += 512) {
        int k = iq >> 5, c0 = (iq & 31) * 4;
        float ax=0.f, ay=0.f, az=0.f, aw=0.f;
#pragma unroll
        for (int b = 0; b < 10; b++) {
            float4 bv = *(const float4*)&s_bT[b*128 + c0];
            float w = s_w1[b*100 + k];
            ax += bv.x*w; ay += bv.y*w; az += bv.z*w; aw += bv.w*w;
        }
        *(float4*)&s_h1[k*128 + c0] =
            make_float4(fmaxf(ax,0.f), fmaxf(ay,0.f), fmaxf(az,0.f), fmaxf(aw,0.f));
    }
    __syncthreads();

    // phase B: h2[j][e] = relu(W2 @ h1), only j < 100 (rows >=100 are dead)
    if (j0 < 100) {
        float4 acc[8];
#pragma unroll
        for (int jj=0;jj<8;jj++) acc[jj] = make_float4(0.f,0.f,0.f,0.f);
#pragma unroll 4
        for (int k = 0; k < 100; k++) {
            float4 h  = *(const float4*)&s_h1[k*128 + e0];
            float4 w0 = *(const float4*)&s_wB[k*128 + j0];
            float4 w1v= *(const float4*)&s_wB[k*128 + j0 + 4];
            float ws[8] = {w0.x,w0.y,w0.z,w0.w,w1v.x,w1v.y,w1v.z,w1v.w};
#pragma unroll
            for (int jj=0;jj<8;jj++) {
                acc[jj].x += h.x*ws[jj]; acc[jj].y += h.y*ws[jj];
                acc[jj].z += h.z*ws[jj]; acc[jj].w += h.w*ws[jj];
            }
        }
#pragma unroll
        for (int jj=0;jj<8;jj++)
            if (j0 + jj < 100)
                *(float4*)&s_h2[(j0+jj)*128 + e0] =
                    make_float4(fmaxf(acc[jj].x,0.f), fmaxf(acc[jj].y,0.f),
                                fmaxf(acc[jj].z,0.f), fmaxf(acc[jj].w,0.f));
    }
    __syncthreads();

    // phase C: out[j][e] = h2 @ W3, chunks of 128 cols; idle warps skip tail
    for (int cb = 0; cb < NW; cb += 128) {
        const int cw = (NW - cb) < 128 ? (NW - cb) : 128;
        for (int i = tid; i < 12800; i += 512) {
            int k = i >> 7, j = i & 127;
            s_wB[i] = (j < cw) ? W3[k*NW + cb + j] : 0.f;
        }
        __syncthreads();
        if (j0 < cw) {
            float4 acc[8];
#pragma unroll
            for (int jj=0;jj<8;jj++) acc[jj] = make_float4(0.f,0.f,0.f,0.f);
#pragma unroll 4
            for (int k = 0; k < 100; k++) {
                float4 h  = *(const float4*)&s_h2[k*128 + e0];
                float4 w0 = *(const float4*)&s_wB[k*128 + j0];
                float4 w1v= *(const float4*)&s_wB[k*128 + j0 + 4];
                float ws[8] = {w0.x,w0.y,w0.z,w0.w,w1v.x,w1v.y,w1v.z,w1v.w};
#pragma unroll
                for (int jj=0;jj<8;jj++) {
                    acc[jj].x += h.x*ws[jj]; acc[jj].y += h.y*ws[jj];
                    acc[jj].z += h.z*ws[jj]; acc[jj].w += h.w*ws[jj];
                }
            }
#pragma unroll
            for (int jj=0;jj<8;jj++)
                if (cb + j0 + jj < NW)
                    *(float4*)&g_wT[(size_t)(cb+j0+jj)*NEDGE + ebase + e0] = acc[jj];
        }
        __syncthreads();
    }
}

__device__ __forceinline__ float red16(float v) {
    v += __shfl_xor_sync(0xffffffffu, v, 8);
    v += __shfl_xor_sync(0xffffffffu, v, 4);
    v += __shfl_xor_sync(0xffffffffu, v, 2);
    v += __shfl_xor_sync(0xffffffffu, v, 1);
    return v;
}
__constant__ int c_ML[3] = {3,5,7};
__constant__ int c_AO[3] = {0,12,32};
__constant__ int c_YO[3] = {0,3,8};
__constant__ int c_FO[3] = {4,16,36};

__device__ __forceinline__ void gate_write(float* fo, const float* out0,
                                           const float* acc)
{
#pragma unroll
    for (int o=0;o<4;o++) fo[o] = fmaxf(out0[o], 0.f);
    float g[12];
#pragma unroll
    for (int j=0;j<12;j++) g[j] = 1.f/(1.f + expf(-out0[4+j]));
#pragma unroll
    for (int l=0;l<3;l++)
#pragma unroll
        for (int o=0;o<4;o++)
#pragma unroll
            for (int m=0;m<7;m++)
                if (m < c_ML[l])
                    fo[c_FO[l] + o*c_ML[l] + m] =
                        acc[c_AO[l] + o*c_ML[l] + m] * g[l*4+o];
}

__device__ __forceinline__ float WT(int idx, size_t e) {
    return g_wT[(size_t)idx*NEDGE + e];
}

__global__ void __launch_bounds__(256) conv0_kernel()
{
    int gt = blockIdx.x*blockDim.x + threadIdx.x;
    int atom = gt >> 4, sub = gt & 15;
    size_t e = (size_t)atom*KNBR + sub;
    const float* Yp = g_Y + e*16;
    float Y[15];
#pragma unroll
    for (int m=0;m<15;m++) Y[m] = Yp[m];
    float out0[16];
#pragma unroll
    for (int o=0;o<16;o++) out0[o] = red16(WT(o,e)*0.5f);
    float acc[60];
#pragma unroll
    for (int l=0;l<3;l++)
#pragma unroll
        for (int o=0;o<4;o++) {
            float s = WT(16 + l*4 + o, e)*0.5f;
#pragma unroll
            for (int m=0;m<7;m++)
                if (m < c_ML[l])
                    acc[c_AO[l]+o*c_ML[l]+m] = red16(s*Y[c_YO[l]+m]);
        }
    if (sub == 0) gate_write(g_featA + (size_t)atom*64, out0, acc);
}

__global__ void __launch_bounds__(256) conv12_kernel(const int* __restrict__ nbr, int dir)
{
    const float* fin = dir ? g_featB : g_featA;
    float* fout      = dir ? g_featA : g_featB;
    int gt = blockIdx.x*blockDim.x + threadIdx.x;
    int atom = gt >> 4, sub = gt & 15;
    size_t e = (size_t)atom*KNBR + sub;
    int nb = nbr[e];
    const float* Yp = g_Y + e*16;
    const float* fj = fin + (size_t)nb*64;
    float Y[15];
#pragma unroll
    for (int m=0;m<15;m++) Y[m] = Yp[m];
    float f0[4];
#pragma unroll
    for (int i=0;i<4;i++) f0[i] = 0.5f*fj[i];
    float out0[16];
#pragma unroll
    for (int o=0;o<16;o++)
        out0[o] = red16(WT(o*4,e)*f0[0] + WT(o*4+1,e)*f0[1] +
                        WT(o*4+2,e)*f0[2] + WT(o*4+3,e)*f0[3]);
    float acc[60];
#pragma unroll
    for (int l=0;l<3;l++) {
        float fl[28];
#pragma unroll
        for (int q=0;q<28;q++)
            if (q < 4*c_ML[l]) fl[q] = 0.5f*fj[c_FO[l]+q];
#pragma unroll
        for (int o=0;o<4;o++) {
            int wb = 64 + l*32 + o*4;
            float s = WT(wb,e)*f0[0]+WT(wb+1,e)*f0[1]+WT(wb+2,e)*f0[2]+WT(wb+3,e)*f0[3];
            float wA[4];
#pragma unroll
            for (int i=0;i<4;i++) wA[i] = WT(wb+16+i, e);
#pragma unroll
            for (int m=0;m<7;m++)
                if (m < c_ML[l]) {
                    float v = s*Y[c_YO[l]+m];
#pragma unroll
                    for (int i=0;i<4;i++) v += wA[i]*fl[i*c_ML[l]+m];
                    acc[c_AO[l]+o*c_ML[l]+m] = red16(v);
                }
        }
    }
    if (sub == 0) gate_write(fout + (size_t)atom*64, out0, acc);
}

__global__ void __launch_bounds__(256) conv3_kernel(const int* __restrict__ nbr)
{
    int gt = blockIdx.x*blockDim.x + threadIdx.x;
    int atom = gt >> 4, sub = gt & 15;
    size_t e = (size_t)atom*KNBR + sub;
    int nb = nbr[e];
    const float* fj = g_featA + (size_t)nb*64;
    float f0[4];
#pragma unroll
    for (int i=0;i<4;i++) f0[i] = 0.5f*fj[i];
#pragma unroll
    for (int o=0;o<64;o++) {
        float v = WT(o*4,e)*f0[0] + WT(o*4+1,e)*f0[1] +
                  WT(o*4+2,e)*f0[2] + WT(o*4+3,e)*f0[3];
        v = red16(v);
        if (sub == 0) g_featB[(size_t)atom*64 + o] = fmaxf(v, 0.f);
    }
}

__global__ void pool1_kernel()
{
    __shared__ float sm[256];
    int b = blockIdx.x, tid = threadIdx.x, t = tid >> 6, f = tid & 63;
    float s = 0.f;
    for (int a = b*512 + t; a < (b+1)*512; a += 4)
        s += g_featB[(size_t)a*64 + f];
    sm[tid] = s;
    __syncthreads();
    if (t == 0) g_part[b*64+f] = sm[f] + sm[64+f] + sm[128+f] + sm[192+f];
}
__global__ void pool2_kernel(const float* __restrict__ lw,
                             const float* __restrict__ lb, float* out)
{
    __shared__ float pooled[64];
    int tid = threadIdx.x;
    if (tid < 64) {
        float s = 0.f;
        for (int b=0;b<64;b++) s += g_part[b*64+tid];
        pooled[tid] = s*(1.f/32768.f);
    }
    __syncthreads();
    if (tid < 10) {
        float s = lb[tid];
        for (int f=0;f<64;f++) s += pooled[f]*lw[f*10+tid];
        out[tid] = s;
    }
}

extern "C" void kernel_launch(void* const* d_in, const int* in_sizes, int n_in,
                              void* d_out, int out_size)
{
    const float *coords=0,*shift=0,*lw=0,*lb=0;
    const float *w1[4]={0,0,0,0}, *w2[4]={0,0,0,0}, *w3[4]={0,0,0,0};
    const int* nbr=0;
    int n1=0, n2=0, n3m=0;
    for (int i=0;i<n_in;i++) {
        switch (in_sizes[i]) {
            case 98304:   coords = (const float*)d_in[i]; break;
            case 1572864: shift  = (const float*)d_in[i]; break;
            case 524288:  nbr    = (const int*)d_in[i];   break;
            case 1000:    if (n1<4) w1[n1++] = (const float*)d_in[i]; break;
            case 10000:   if (n2<4) w2[n2++] = (const float*)d_in[i]; break;
            case 2800:    w3[0] = (const float*)d_in[i];  break;
            case 16000:   if (n3m<2) w3[1+n3m++] = (const float*)d_in[i]; break;
            case 25600:   w3[3] = (const float*)d_in[i];  break;
            case 640:     lw = (const float*)d_in[i];     break;
            case 10:      lb = (const float*)d_in[i];     break;
            default: break;
        }
    }
    if (!coords || !shift || !nbr || !lw || !lb ||
        !w1[0]||!w1[1]||!w1[2]||!w1[3] || !w2[0]||!w2[1]||!w2[2]||!w2[3] ||
        !w3[0]||!w3[1]||!w3[2]||!w3[3]) {
        pool2_kernel<<<1, 128>>>(lw ? lw : (const float*)d_in[0],
                                 lb ? lb : (const float*)d_in[0], (float*)d_out);
        return;
    }
    float* out = (float*)d_out;

    cudaFuncSetAttribute(radial_kernel<28>,  cudaFuncAttributeMaxDynamicSharedMemorySize, SMEM_BYTES);
    cudaFuncSetAttribute(radial_kernel<160>, cudaFuncAttributeMaxDynamicSharedMemorySize, SMEM_BYTES);
    cudaFuncSetAttribute(radial_kernel<256>, cudaFuncAttributeMaxDynamicSharedMemorySize, SMEM_BYTES);

    geom_kernel<<<NEDGE/256, 256>>>(coords, shift, nbr);
    radial_kernel<28><<<NEDGE/128, 512, SMEM_BYTES>>>(w1[0], w2[0], w3[0]);
    conv0_kernel<<<NATOM*16/256, 256>>>();
    radial_kernel<160><<<NEDGE/128, 512, SMEM_BYTES>>>(w1[1], w2[1], w3[1]);
    conv12_kernel<<<NATOM*16/256, 256>>>(nbr, 0);
    radial_kernel<160><<<NEDGE/128, 512, SMEM_BYTES>>>(w1[2], w2[2], w3[2]);
    conv12_kernel<<<NATOM*16/256, 256>>>(nbr, 1);
    radial_kernel<256><<<NEDGE/128, 512, SMEM_BYTES>>>(w1[3], w2[3], w3[3]);
    conv3_kernel<<<NATOM*16/256, 256>>>(nbr);
    pool1_kernel<<<64, 256>>>();
    pool2_kernel<<<1, 128>>>(lw, lb, out);
}